// round 3
// baseline (speedup 1.0000x reference)
#include <cuda_runtime.h>
#include <cstdint>

typedef unsigned long long ull;

#define NHALF   4096
#define NROWS   8192
#define D       128
#define TM      128
#define TN      128
#define KC      16
#define NSPLIT  8
#define SHIFT   20.0f
#define INV_SQRT_T 3.1622776601683795f   // 1/sqrt(0.1)

// Scratch (no allocations allowed -> __device__ globals)
__device__ float g_zs[NROWS * D];            // normalized * (1/sqrt(T)) rows
__device__ float g_pos[NHALF];               // pos_i = 2 * dot(zs_i, zs_{i+N}) = 2*cos/T
__device__ float g_partial[NSPLIT * NROWS];  // per-split row sums of exp(sim-20), excl diag

// ---------------- packed f32x2 helpers ----------------
__device__ __forceinline__ ull pack2(float x, float y) {
    ull r; asm("mov.b64 %0, {%1, %2};" : "=l"(r) : "f"(x), "f"(y)); return r;
}
__device__ __forceinline__ float2 unpack2(ull v) {
    float2 f; asm("mov.b64 {%0, %1}, %2;" : "=f"(f.x), "=f"(f.y) : "l"(v)); return f;
}
__device__ __forceinline__ void fma2(ull& d, ull a, ull b) {
    asm("fma.rn.f32x2 %0, %1, %2, %0;" : "+l"(d) : "l"(a), "l"(b));
}

// ---------------- 1) normalize: zs = z / (max(||z||,eps) * sqrt(T)) ----------------
__global__ void norm_kernel(const float* __restrict__ z1, const float* __restrict__ z2) {
    int w    = (blockIdx.x * blockDim.x + threadIdx.x) >> 5;  // one warp per row
    int lane = threadIdx.x & 31;
    if (w >= NROWS) return;
    const float* src = (w < NHALF) ? (z1 + (size_t)w * D) : (z2 + (size_t)(w - NHALF) * D);
    float4 v = reinterpret_cast<const float4*>(src)[lane];    // 32 lanes * 4 = 128
    float ss = v.x * v.x + v.y * v.y + v.z * v.z + v.w * v.w;
    #pragma unroll
    for (int o = 16; o; o >>= 1) ss += __shfl_xor_sync(0xFFFFFFFFu, ss, o);
    float nrm = sqrtf(ss);
    float s = INV_SQRT_T / fmaxf(nrm, 1e-8f);
    float4 o4 = make_float4(v.x * s, v.y * s, v.z * s, v.w * s);
    reinterpret_cast<float4*>(g_zs + (size_t)w * D)[lane] = o4;
}

// ---------------- 2) pos_i = 2 * dot(zs_i, zs_{i+N}) ----------------
__global__ void pos_kernel() {
    int w    = (blockIdx.x * blockDim.x + threadIdx.x) >> 5;  // one warp per i
    int lane = threadIdx.x & 31;
    if (w >= NHALF) return;
    float4 a = reinterpret_cast<const float4*>(g_zs + (size_t)w * D)[lane];
    float4 b = reinterpret_cast<const float4*>(g_zs + (size_t)(w + NHALF) * D)[lane];
    float d = a.x * b.x + a.y * b.y + a.z * b.z + a.w * b.w;
    #pragma unroll
    for (int o = 16; o; o >>= 1) d += __shfl_xor_sync(0xFFFFFFFFu, d, o);
    if (lane == 0) g_pos[w] = 2.0f * d;
}

// ---------------- 3) fused GEMM + exp + row-sum ----------------
// grid = (64 i-tiles, NSPLIT j-splits), block = 256 threads.
// Each block: one 128-row i-tile, 8 j-tiles; writes partial[split][row].
__global__ __launch_bounds__(256, 2) void gemm_kernel() {
    __shared__ float As[KC][TM];     // k-major
    __shared__ float Bs[KC][TN];
    __shared__ float rowacc[TM];

    const int tid   = threadIdx.x;
    const int tx    = tid & 15;          // col group (8 cols)
    const int ty    = tid >> 4;          // row group (8 rows)
    const int bi    = blockIdx.x;
    const int split = blockIdx.y;
    const int base_i = bi * TM;

    if (tid < TM) rowacc[tid] = 0.0f;

    const int loadRow = tid >> 1;        // 0..127
    const int loadCol = (tid & 1) * 8;   // 0 or 8

    for (int t = 0; t < (64 / NSPLIT); ++t) {
        const int jt     = split * (64 / NSPLIT) + t;
        const int base_j = jt * TN;

        ull acc[4][8];                   // row-pairs x 8 cols, packed f32x2
        #pragma unroll
        for (int p = 0; p < 4; ++p)
            #pragma unroll
            for (int v = 0; v < 8; ++v) acc[p][v] = 0ULL;

        for (int kc = 0; kc < D; kc += KC) {
            __syncthreads();  // protect prior chunk's reads (and rowacc zero on first pass)
            {
                const float* ga = g_zs + (size_t)(base_i + loadRow) * D + kc + loadCol;
                float4 a0 = reinterpret_cast<const float4*>(ga)[0];
                float4 a1 = reinterpret_cast<const float4*>(ga)[1];
                As[loadCol + 0][loadRow] = a0.x; As[loadCol + 1][loadRow] = a0.y;
                As[loadCol + 2][loadRow] = a0.z; As[loadCol + 3][loadRow] = a0.w;
                As[loadCol + 4][loadRow] = a1.x; As[loadCol + 5][loadRow] = a1.y;
                As[loadCol + 6][loadRow] = a1.z; As[loadCol + 7][loadRow] = a1.w;

                const float* gb = g_zs + (size_t)(base_j + loadRow) * D + kc + loadCol;
                float4 b0 = reinterpret_cast<const float4*>(gb)[0];
                float4 b1 = reinterpret_cast<const float4*>(gb)[1];
                Bs[loadCol + 0][loadRow] = b0.x; Bs[loadCol + 1][loadRow] = b0.y;
                Bs[loadCol + 2][loadRow] = b0.z; Bs[loadCol + 3][loadRow] = b0.w;
                Bs[loadCol + 4][loadRow] = b1.x; Bs[loadCol + 5][loadRow] = b1.y;
                Bs[loadCol + 6][loadRow] = b1.z; Bs[loadCol + 7][loadRow] = b1.w;
            }
            __syncthreads();

            #pragma unroll
            for (int k = 0; k < KC; ++k) {
                const ull* ap = reinterpret_cast<const ull*>(&As[k][ty * 8]);
                ull a0 = ap[0], a1 = ap[1], a2 = ap[2], a3 = ap[3];
                const float4* bp = reinterpret_cast<const float4*>(&Bs[k][tx * 8]);
                float4 b0 = bp[0], b1 = bp[1];
                ull bd[8];
                bd[0] = pack2(b0.x, b0.x); bd[1] = pack2(b0.y, b0.y);
                bd[2] = pack2(b0.z, b0.z); bd[3] = pack2(b0.w, b0.w);
                bd[4] = pack2(b1.x, b1.x); bd[5] = pack2(b1.y, b1.y);
                bd[6] = pack2(b1.z, b1.z); bd[7] = pack2(b1.w, b1.w);
                #pragma unroll
                for (int v = 0; v < 8; ++v) {
                    fma2(acc[0][v], a0, bd[v]);
                    fma2(acc[1][v], a1, bd[v]);
                    fma2(acc[2][v], a2, bd[v]);
                    fma2(acc[3][v], a3, bd[v]);
                }
            }
        }

        // Epilogue: exp(sim - 20), skip diagonal, per-row sums
        float rsum[8];
        #pragma unroll
        for (int u = 0; u < 8; ++u) rsum[u] = 0.0f;
        #pragma unroll
        for (int p = 0; p < 4; ++p) {
            const int gr0 = base_i + ty * 8 + 2 * p;
            #pragma unroll
            for (int v = 0; v < 8; ++v) {
                float2 f = unpack2(acc[p][v]);
                int gc = base_j + tx * 8 + v;
                if (gr0 != gc)     rsum[2 * p]     += __expf(f.x - SHIFT);
                if (gr0 + 1 != gc) rsum[2 * p + 1] += __expf(f.y - SHIFT);
            }
        }
        // reduce across the 16 tx threads (half-warp butterfly), accumulate in smem.
        // Each rowacc slot has a unique writer thread (tx==0 of half-warp ty) -> no atomics.
        #pragma unroll
        for (int u = 0; u < 8; ++u) {
            float v = rsum[u];
            #pragma unroll
            for (int o = 8; o; o >>= 1) v += __shfl_xor_sync(0xFFFFFFFFu, v, o);
            if (tx == 0) rowacc[ty * 8 + u] += v;
        }
    }

    __syncthreads();
    if (tid < TM) g_partial[split * NROWS + base_i + tid] = rowacc[tid];
}

// ---------------- 4) final reduction ----------------
__global__ void final_kernel(float* __restrict__ out) {
    __shared__ float red[256];
    float local = 0.0f;
    for (int r = threadIdx.x; r < NROWS; r += 256) {
        float s = 0.0f;
        #pragma unroll
        for (int p = 0; p < NSPLIT; ++p) s += g_partial[p * NROWS + r];
        float pv = g_pos[r & (NHALF - 1)];
        s += __expf(pv - SHIFT);               // the pos logit column
        local += (logf(s) + SHIFT) - pv;       // lse - pos
    }
    red[threadIdx.x] = local;
    __syncthreads();
    for (int o = 128; o; o >>= 1) {
        if (threadIdx.x < o) red[threadIdx.x] += red[threadIdx.x + o];
        __syncthreads();
    }
    if (threadIdx.x == 0)
        out[0] = red[0] * (1.0f / ((float)NROWS * (float)NROWS));  // /M then /M
}

// ---------------- launcher ----------------
extern "C" void kernel_launch(void* const* d_in, const int* in_sizes, int n_in,
                              void* d_out, int out_size) {
    const float* z1 = (const float*)d_in[0];
    const float* z2 = (const float*)d_in[1];
    float* out = (float*)d_out;
    (void)in_sizes; (void)n_in; (void)out_size;

    norm_kernel<<<NROWS / 8, 256>>>(z1, z2);       // 8 warps/block, 1 warp/row
    pos_kernel<<<NHALF / 8, 256>>>();
    dim3 grid(NROWS / TM, NSPLIT);
    gemm_kernel<<<grid, 256>>>();
    final_kernel<<<1, 256>>>(out);
}

// round 6
// speedup vs baseline: 3.4752x; 3.4752x over previous
#include <cuda_runtime.h>
#include <cuda_bf16.h>
#include <cstdint>

#define NHALF   4096
#define NROWS   8192
#define D       128
#define NBI     64                        // i blocks (128 rows each)
#define NBJ     128                       // j blocks (64 cols each)
#define NSLOT   (NBJ * 2)                 // 2 n-warps per j block
#define SHIFT2  28.853900817779268f       // 20 * log2(e)
#define LOG2E   1.4426950408889634f
#define SCALE_NORM 3.79828256502352f      // sqrt(log2(e) / 0.1): folded into rows

// -------- scratch (__device__ globals; no allocations allowed) --------
__device__ __nv_bfloat16 g_zb[NROWS * D];     // normalized rows * sqrt(log2e/T)
__device__ float g_pos[NHALF];                // pos_i = 2*cos_i/T (fp32)
__device__ float g_partial[NSLOT * NROWS];    // per-(jblock,nwarp) row sums
__device__ float g_blk[32];

__device__ __forceinline__ uint32_t smem_u32(const void* p) {
    uint32_t a;
    asm("{ .reg .u64 t; cvta.to.shared.u64 t, %1; cvt.u32.u64 %0, t; }" : "=r"(a) : "l"(p));
    return a;
}
__device__ __forceinline__ void ldsm4(uint32_t* r, uint32_t addr) {
    asm volatile("ldmatrix.sync.aligned.m8n8.x4.shared.b16 {%0,%1,%2,%3}, [%4];"
                 : "=r"(r[0]), "=r"(r[1]), "=r"(r[2]), "=r"(r[3]) : "r"(addr));
}
__device__ __forceinline__ void mma16816(float* c, const uint32_t* a, const uint32_t* b) {
    asm volatile(
        "mma.sync.aligned.m16n8k16.row.col.f32.bf16.bf16.f32 "
        "{%0,%1,%2,%3}, {%4,%5,%6,%7}, {%8,%9}, {%0,%1,%2,%3};"
        : "+f"(c[0]), "+f"(c[1]), "+f"(c[2]), "+f"(c[3])
        : "r"(a[0]), "r"(a[1]), "r"(a[2]), "r"(a[3]), "r"(b[0]), "r"(b[1]));
}

// ---------------- 1) normalize + scale + bf16 ----------------
__global__ void norm_kernel(const float* __restrict__ z1, const float* __restrict__ z2) {
    int w    = (blockIdx.x * blockDim.x + threadIdx.x) >> 5;
    int lane = threadIdx.x & 31;
    if (w >= NROWS) return;
    const float* src = (w < NHALF) ? (z1 + (size_t)w * D) : (z2 + (size_t)(w - NHALF) * D);
    float4 v = reinterpret_cast<const float4*>(src)[lane];
    float ss = v.x * v.x + v.y * v.y + v.z * v.z + v.w * v.w;
    #pragma unroll
    for (int o = 16; o; o >>= 1) ss += __shfl_xor_sync(0xFFFFFFFFu, ss, o);
    float s = SCALE_NORM / fmaxf(sqrtf(ss), 1e-8f);
    __nv_bfloat162 h0 = __floats2bfloat162_rn(v.x * s, v.y * s);
    __nv_bfloat162 h1 = __floats2bfloat162_rn(v.z * s, v.w * s);
    __nv_bfloat162* dst = reinterpret_cast<__nv_bfloat162*>(g_zb + (size_t)w * D);
    dst[lane * 2 + 0] = h0;
    dst[lane * 2 + 1] = h1;
}

// ---------------- 2) pos_i = 2*cos(z1_i, z2_i)/T (fp32) ----------------
__global__ void pos_kernel(const float* __restrict__ z1, const float* __restrict__ z2) {
    int w    = (blockIdx.x * blockDim.x + threadIdx.x) >> 5;
    int lane = threadIdx.x & 31;
    if (w >= NHALF) return;
    float4 a = reinterpret_cast<const float4*>(z1 + (size_t)w * D)[lane];
    float4 b = reinterpret_cast<const float4*>(z2 + (size_t)w * D)[lane];
    float ab = a.x * b.x + a.y * b.y + a.z * b.z + a.w * b.w;
    float aa = a.x * a.x + a.y * a.y + a.z * a.z + a.w * a.w;
    float bb = b.x * b.x + b.y * b.y + b.z * b.z + b.w * b.w;
    #pragma unroll
    for (int o = 16; o; o >>= 1) {
        ab += __shfl_xor_sync(0xFFFFFFFFu, ab, o);
        aa += __shfl_xor_sync(0xFFFFFFFFu, aa, o);
        bb += __shfl_xor_sync(0xFFFFFFFFu, bb, o);
    }
    if (lane == 0) {
        float na = fmaxf(sqrtf(aa), 1e-8f);
        float nb = fmaxf(sqrtf(bb), 1e-8f);
        g_pos[w] = 2.0f * (ab / (na * nb)) * 10.0f;
    }
}

// ---------------- 3) HMMA GEMM tile + exp2/row-sum epilogue ----------------
// CTA: 128(M) x 64(N), K=128. 8 warps = 4(m) x 2(n), warp tile 32x32.
// SMEM rows are 256B (128 bf16); 16B chunk c of row r stored at chunk (c ^ (r&7)).
__global__ __launch_bounds__(256) void gemm_kernel() {
    __shared__ __align__(16) unsigned char smem[49152];   // A:32KB, B at +32768:16KB
    const uint32_t sb = smem_u32(smem);
    const int tid  = threadIdx.x;
    const int wid  = tid >> 5;
    const int lane = tid & 31;
    const int base_i = blockIdx.x * 128;
    const int base_j = blockIdx.y * 64;

    // ---- global -> smem (swizzled) ----
    {
        int r  = tid >> 1;                 // A: 128 rows, 2 threads/row
        int c0 = (tid & 1) * 8;
        const uint4* gA = reinterpret_cast<const uint4*>(g_zb + (size_t)(base_i + r) * D);
        #pragma unroll
        for (int c = 0; c < 8; ++c) {
            int ch = c0 + c;
            uint32_t off = (uint32_t)r * 256u + (uint32_t)((ch ^ (r & 7)) * 16);
            *reinterpret_cast<uint4*>(smem + off) = gA[ch];
        }
        int rb = tid >> 2;                 // B: 64 rows, 4 threads/row
        int cb = (tid & 3) * 4;
        const uint4* gB = reinterpret_cast<const uint4*>(g_zb + (size_t)(base_j + rb) * D);
        #pragma unroll
        for (int c = 0; c < 4; ++c) {
            int ch = cb + c;
            uint32_t off = 32768u + (uint32_t)rb * 256u + (uint32_t)((ch ^ (rb & 7)) * 16);
            *reinterpret_cast<uint4*>(smem + off) = gB[ch];
        }
    }
    __syncthreads();

    const int warp_m = (wid & 3) * 32;
    const int warp_n = (wid >> 2) * 32;
    const int lr = lane & 7;
    const int q  = lane >> 3;

    // ldmatrix lane-role derivation (x4 = 4 8x8 matrices, lanes 0-7/8-15/16-23/24-31):
    // A frag: q0:(row+0,ck0) q1:(row+8,ck0) q2:(row+0,ck1) q3:(row+8,ck1)
    // B pair: q0:(row+0,ck0) q1:(row+0,ck1) q2:(row+8,ck0) q3:(row+8,ck1)
    const int rowA0 = warp_m + lr + (q & 1) * 8;          // + mt*16
    const int ckA   = q >> 1;
    const int rowB0 = warp_n + lr + (q >> 1) * 8;         // + pair*16
    const int ckB   = q & 1;

    float acc[2][4][4];
    #pragma unroll
    for (int mt = 0; mt < 2; ++mt)
        #pragma unroll
        for (int nt = 0; nt < 4; ++nt)
            #pragma unroll
            for (int e = 0; e < 4; ++e) acc[mt][nt][e] = 0.0f;

    #pragma unroll
    for (int ks = 0; ks < 8; ++ks) {
        uint32_t a[2][4], b[4][2];
        #pragma unroll
        for (int mt = 0; mt < 2; ++mt) {
            int r = rowA0 + mt * 16;
            int ch = ks * 2 + ckA;
            uint32_t addr = sb + (uint32_t)r * 256u + (uint32_t)((ch ^ (r & 7)) * 16);
            ldsm4(a[mt], addr);
        }
        #pragma unroll
        for (int p = 0; p < 2; ++p) {
            int r = rowB0 + p * 16;
            int ch = ks * 2 + ckB;
            uint32_t addr = sb + 32768u + (uint32_t)r * 256u + (uint32_t)((ch ^ (r & 7)) * 16);
            uint32_t t[4];
            ldsm4(t, addr);
            b[p * 2 + 0][0] = t[0]; b[p * 2 + 0][1] = t[1];
            b[p * 2 + 1][0] = t[2]; b[p * 2 + 1][1] = t[3];
        }
        #pragma unroll
        for (int mt = 0; mt < 2; ++mt)
            #pragma unroll
            for (int nt = 0; nt < 4; ++nt)
                mma16816(acc[mt][nt], a[mt], b[nt]);
    }

    // ---- epilogue: exp2(sim - 20*log2e), skip diagonal, per-row sums ----
    // C frag: c0,c1 -> row l/4,   cols 2(l&3), 2(l&3)+1
    //         c2,c3 -> row l/4+8, same cols
    float rs[2][2];    // [mt][row half]
    #pragma unroll
    for (int mt = 0; mt < 2; ++mt) {
        const int r0 = base_i + warp_m + mt * 16 + (lane >> 2);
        const int r1 = r0 + 8;
        float s0 = 0.0f, s1 = 0.0f;
        #pragma unroll
        for (int nt = 0; nt < 4; ++nt) {
            const int gc = base_j + warp_n + nt * 8 + (lane & 3) * 2;
            float v0 = acc[mt][nt][0], v1 = acc[mt][nt][1];
            float v2 = acc[mt][nt][2], v3 = acc[mt][nt][3];
            if (gc     != r0) s0 += exp2f(v0 - SHIFT2);
            if (gc + 1 != r0) s0 += exp2f(v1 - SHIFT2);
            if (gc     != r1) s1 += exp2f(v2 - SHIFT2);
            if (gc + 1 != r1) s1 += exp2f(v3 - SHIFT2);
        }
        rs[mt][0] = s0; rs[mt][1] = s1;
    }
    // quad-reduce (lanes sharing a row differ only in lane&3)
    #pragma unroll
    for (int mt = 0; mt < 2; ++mt)
        #pragma unroll
        for (int h = 0; h < 2; ++h) {
            float v = rs[mt][h];
            v += __shfl_xor_sync(0xFFFFFFFFu, v, 1);
            v += __shfl_xor_sync(0xFFFFFFFFu, v, 2);
            rs[mt][h] = v;
        }
    if ((lane & 3) == 0) {
        const int slot = blockIdx.y * 2 + (wid >> 2);
        #pragma unroll
        for (int mt = 0; mt < 2; ++mt) {
            int r0 = base_i + warp_m + mt * 16 + (lane >> 2);
            g_partial[(size_t)slot * NROWS + r0]     = rs[mt][0];
            g_partial[(size_t)slot * NROWS + r0 + 8] = rs[mt][1];
        }
    }
}

// ---------------- 4) reduction stage 1 ----------------
__global__ void reduce1_kernel() {
    __shared__ float red[256];
    int r = blockIdx.x * 256 + threadIdx.x;       // 32*256 = 8192 rows
    float s = 0.0f;
    for (int p = 0; p < NSLOT; ++p) s += g_partial[(size_t)p * NROWS + r];
    float pv = g_pos[r & (NHALF - 1)];
    s += exp2f(pv * LOG2E - SHIFT2);              // the pos logit column
    red[threadIdx.x] = (logf(s) + 20.0f) - pv;    // lse - pos
    __syncthreads();
    #pragma unroll
    for (int o = 128; o; o >>= 1) {
        if (threadIdx.x < o) red[threadIdx.x] += red[threadIdx.x + o];
        __syncthreads();
    }
    if (threadIdx.x == 0) g_blk[blockIdx.x] = red[0];
}

// ---------------- 5) reduction stage 2 ----------------
__global__ void reduce2_kernel(float* __restrict__ out) {
    float v = g_blk[threadIdx.x];
    #pragma unroll
    for (int o = 16; o; o >>= 1) v += __shfl_xor_sync(0xFFFFFFFFu, v, o);
    if (threadIdx.x == 0)
        out[0] = v * (1.0f / ((float)NROWS * (float)NROWS));
}

// ---------------- launcher ----------------
extern "C" void kernel_launch(void* const* d_in, const int* in_sizes, int n_in,
                              void* d_out, int out_size) {
    const float* z1 = (const float*)d_in[0];
    const float* z2 = (const float*)d_in[1];
    float* out = (float*)d_out;
    (void)in_sizes; (void)n_in; (void)out_size;

    norm_kernel<<<NROWS / 8, 256>>>(z1, z2);
    pos_kernel<<<NHALF / 8, 256>>>(z1, z2);
    dim3 grid(NBI, NBJ);
    gemm_kernel<<<grid, 256>>>();
    reduce1_kernel<<<32, 256>>>();
    reduce2_kernel<<<1, 32>>>(out);
}

// round 9
// speedup vs baseline: 9.1248x; 2.6256x over previous
#include <cuda_runtime.h>
#include <cuda_bf16.h>
#include <cstdint>

#define NHALF   4096
#define NROWS   8192
#define D       128
#define NB      64                        // 128-row blocks
#define NTRI    2080                      // NB*(NB+1)/2 triangular tiles
#define SHIFT2  28.853900817779268f       // 20 * log2(e)
#define LOG2E   1.4426950408889634f
#define SCALE_NORM 3.79828256502352f      // sqrt(log2(e)/0.1), folded into rows

// -------- scratch (__device__ globals; no allocations allowed) --------
__device__ __nv_bfloat16 g_zb[NROWS * D];    // normalized rows * sqrt(log2e/T)
__device__ float g_pos[NHALF];               // pos_i = 2*cos_i/T (fp32)
__device__ float g_partial[NB * NROWS];      // [slot][row] exp row-sum partials
__device__ float g_blk[32];

__device__ __forceinline__ uint32_t smem_u32(const void* p) {
    uint32_t a;
    asm("{ .reg .u64 t; cvta.to.shared.u64 t, %1; cvt.u32.u64 %0, t; }" : "=r"(a) : "l"(p));
    return a;
}
__device__ __forceinline__ void ldsm4(uint32_t* r, uint32_t addr) {
    asm volatile("ldmatrix.sync.aligned.m8n8.x4.shared.b16 {%0,%1,%2,%3}, [%4];"
                 : "=r"(r[0]), "=r"(r[1]), "=r"(r[2]), "=r"(r[3]) : "r"(addr));
}
__device__ __forceinline__ void mma16816(float* c, const uint32_t* a, const uint32_t* b) {
    asm volatile(
        "mma.sync.aligned.m16n8k16.row.col.f32.bf16.bf16.f32 "
        "{%0,%1,%2,%3}, {%4,%5,%6,%7}, {%8,%9}, {%0,%1,%2,%3};"
        : "+f"(c[0]), "+f"(c[1]), "+f"(c[2]), "+f"(c[3])
        : "r"(a[0]), "r"(a[1]), "r"(a[2]), "r"(a[3]), "r"(b[0]), "r"(b[1]));
}
__device__ __forceinline__ float ex2(float x) {
    float y; asm("ex2.approx.ftz.f32 %0, %1;" : "=f"(y) : "f"(x)); return y;
}

// ---------------- 1) fused normalize(+bf16) + pos ----------------
__global__ void normpos_kernel(const float* __restrict__ z1, const float* __restrict__ z2) {
    int w    = (blockIdx.x * blockDim.x + threadIdx.x) >> 5;  // pair index
    int lane = threadIdx.x & 31;
    if (w >= NHALF) return;
    float4 a = reinterpret_cast<const float4*>(z1 + (size_t)w * D)[lane];
    float4 b = reinterpret_cast<const float4*>(z2 + (size_t)w * D)[lane];
    float aa = a.x * a.x + a.y * a.y + a.z * a.z + a.w * a.w;
    float bb = b.x * b.x + b.y * b.y + b.z * b.z + b.w * b.w;
    float ab = a.x * b.x + a.y * b.y + a.z * b.z + a.w * b.w;
    #pragma unroll
    for (int o = 16; o; o >>= 1) {
        aa += __shfl_xor_sync(0xFFFFFFFFu, aa, o);
        bb += __shfl_xor_sync(0xFFFFFFFFu, bb, o);
        ab += __shfl_xor_sync(0xFFFFFFFFu, ab, o);
    }
    float na = fmaxf(sqrtf(aa), 1e-8f);
    float nb = fmaxf(sqrtf(bb), 1e-8f);
    float sa = SCALE_NORM / na, sb = SCALE_NORM / nb;
    __nv_bfloat162* da = reinterpret_cast<__nv_bfloat162*>(g_zb + (size_t)w * D);
    __nv_bfloat162* db = reinterpret_cast<__nv_bfloat162*>(g_zb + (size_t)(w + NHALF) * D);
    da[lane * 2 + 0] = __floats2bfloat162_rn(a.x * sa, a.y * sa);
    da[lane * 2 + 1] = __floats2bfloat162_rn(a.z * sa, a.w * sa);
    db[lane * 2 + 0] = __floats2bfloat162_rn(b.x * sb, b.y * sb);
    db[lane * 2 + 1] = __floats2bfloat162_rn(b.z * sb, b.w * sb);
    if (lane == 0) g_pos[w] = 20.0f * ab / (na * nb);     // 2*cos/T, T=0.1
}

// ---------------- 2) triangular HMMA tile: row-sums + col-sums ----------------
// CTA: one 128x128 tile (bi <= bj). 8 warps = 4(m) x 2(n), warp tile 32x64.
// K split into two 64-halves; smem per half: A 16KB + B 16KB (static 32KB).
// 128B smem rows (64 bf16), 16B chunk c of row r stored at chunk (c ^ (r&7)).
__global__ __launch_bounds__(256) void gemm_kernel() {
    __shared__ __align__(16) unsigned char smem[32768];   // A:16KB, B at +16384
    const uint32_t sb = smem_u32(smem);
    const int tid  = threadIdx.x;
    const int wid  = tid >> 5;
    const int lane = tid & 31;

    // triangular index: t -> (bi, bj) with bi <= bj
    int t = blockIdx.x;
    int bj = (int)((sqrtf(8.0f * (float)t + 1.0f) - 1.0f) * 0.5f);
    while ((bj + 1) * (bj + 2) / 2 <= t) ++bj;
    while (bj * (bj + 1) / 2 > t) --bj;
    int bi = t - bj * (bj + 1) / 2;
    const int base_i = bi * 128;
    const int base_j = bj * 128;
    const bool isdiag = (bi == bj);

    const int warp_m = (wid & 3) * 32;
    const int warp_n = (wid >> 2) * 64;
    const int lr = lane & 7;
    const int q  = lane >> 3;
    const int rowA0 = warp_m + lr + (q & 1) * 8;
    const int ckA   = q >> 1;
    const int rowB0 = warp_n + lr + (q >> 1) * 8;
    const int ckB   = q & 1;

    float acc[2][8][4];
    #pragma unroll
    for (int mt = 0; mt < 2; ++mt)
        #pragma unroll
        for (int nt = 0; nt < 8; ++nt)
            #pragma unroll
            for (int e = 0; e < 4; ++e) acc[mt][nt][e] = 0.0f;

    const int ldr = tid >> 1;            // 0..127
    const int ldc = (tid & 1) * 4;       // chunk base

    #pragma unroll
    for (int kh = 0; kh < 2; ++kh) {
        __syncthreads();
        {
            const uint4* gA = reinterpret_cast<const uint4*>(g_zb + (size_t)(base_i + ldr) * D + kh * 64);
            const uint4* gB = reinterpret_cast<const uint4*>(g_zb + (size_t)(base_j + ldr) * D + kh * 64);
            #pragma unroll
            for (int c = 0; c < 4; ++c) {
                int ch = ldc + c;
                uint32_t off = (uint32_t)ldr * 128u + (uint32_t)((ch ^ (ldr & 7)) * 16);
                *reinterpret_cast<uint4*>(smem + off)          = gA[ch];
                *reinterpret_cast<uint4*>(smem + 16384u + off) = gB[ch];
            }
        }
        __syncthreads();

        #pragma unroll
        for (int ks = 0; ks < 4; ++ks) {
            uint32_t a[2][4], b[8][2];
            #pragma unroll
            for (int mt = 0; mt < 2; ++mt) {
                int r = rowA0 + mt * 16;
                int ch = ks * 2 + ckA;
                ldsm4(a[mt], sb + (uint32_t)r * 128u + (uint32_t)((ch ^ (r & 7)) * 16));
            }
            #pragma unroll
            for (int p = 0; p < 4; ++p) {
                int r = rowB0 + p * 16;
                int ch = ks * 2 + ckB;
                uint32_t tt[4];
                ldsm4(tt, sb + 16384u + (uint32_t)r * 128u + (uint32_t)((ch ^ (r & 7)) * 16));
                b[p * 2 + 0][0] = tt[0]; b[p * 2 + 0][1] = tt[1];
                b[p * 2 + 1][0] = tt[2]; b[p * 2 + 1][1] = tt[3];
            }
            #pragma unroll
            for (int mt = 0; mt < 2; ++mt)
                #pragma unroll
                for (int nt = 0; nt < 8; ++nt)
                    mma16816(acc[mt][nt], a[mt], b[nt]);
        }
    }

    // ---- epilogue ----
    // C frag: c0,c1 -> row l/4, cols 2(l&3)+{0,1}; c2,c3 -> row l/4+8.
    float rs[2][2] = {{0.f, 0.f}, {0.f, 0.f}};
    float cs[8][2];
    #pragma unroll
    for (int nt = 0; nt < 8; ++nt) { cs[nt][0] = 0.f; cs[nt][1] = 0.f; }

    #pragma unroll
    for (int mt = 0; mt < 2; ++mt) {
        const int r0 = base_i + warp_m + mt * 16 + (lane >> 2);
        const int r1 = r0 + 8;
        #pragma unroll
        for (int nt = 0; nt < 8; ++nt) {
            const int gc = base_j + warp_n + nt * 8 + (lane & 3) * 2;
            float e0 = ex2(acc[mt][nt][0] - SHIFT2);
            float e1 = ex2(acc[mt][nt][1] - SHIFT2);
            float e2 = ex2(acc[mt][nt][2] - SHIFT2);
            float e3 = ex2(acc[mt][nt][3] - SHIFT2);
            if (isdiag) {
                if (gc     == r0) e0 = 0.f;
                if (gc + 1 == r0) e1 = 0.f;
                if (gc     == r1) e2 = 0.f;
                if (gc + 1 == r1) e3 = 0.f;
            }
            rs[mt][0] += e0 + e1;
            rs[mt][1] += e2 + e3;
            cs[nt][0] += e0 + e2;
            cs[nt][1] += e1 + e3;
        }
    }

    // row-sums: quad-reduce within warp (lanes sharing a row differ in lane&3)
    #pragma unroll
    for (int mt = 0; mt < 2; ++mt)
        #pragma unroll
        for (int h = 0; h < 2; ++h) {
            float v = rs[mt][h];
            v += __shfl_xor_sync(0xFFFFFFFFu, v, 1);
            v += __shfl_xor_sync(0xFFFFFFFFu, v, 2);
            rs[mt][h] = v;
        }
    // col-sums: reduce across the 8 row-groups of the warp (xor 4,8,16)
    if (!isdiag) {
        #pragma unroll
        for (int nt = 0; nt < 8; ++nt)
            #pragma unroll
            for (int e = 0; e < 2; ++e) {
                float v = cs[nt][e];
                v += __shfl_xor_sync(0xFFFFFFFFu, v, 4);
                v += __shfl_xor_sync(0xFFFFFFFFu, v, 8);
                v += __shfl_xor_sync(0xFFFFFFFFu, v, 16);
                cs[nt][e] = v;
            }
    }

    __syncthreads();   // operand smem no longer needed; reuse for reductions
    float* rowacc = reinterpret_cast<float*>(smem);          // [2][128] per n-half
    float* colacc = reinterpret_cast<float*>(smem) + 256;    // [4][128] per m-group

    // rowacc: each warp's 32 rows, keyed by n-half (wid>>2). BOTH halves must
    // be summed before hitting g_partial (this was the R7 bug).
    if ((lane & 3) == 0) {
        #pragma unroll
        for (int mt = 0; mt < 2; ++mt) {
            int r = warp_m + mt * 16 + (lane >> 2);
            rowacc[(wid >> 2) * 128 + r]     = rs[mt][0];
            rowacc[(wid >> 2) * 128 + r + 8] = rs[mt][1];
        }
    }
    if (!isdiag && lane < 4) {
        #pragma unroll
        for (int nt = 0; nt < 8; ++nt) {
            int col = warp_n + nt * 8 + lane * 2;
            colacc[(wid & 3) * 128 + col]     = cs[nt][0];
            colacc[(wid & 3) * 128 + col + 1] = cs[nt][1];
        }
    }
    __syncthreads();

    if (tid < 128) {
        // slot bj <- rows of block bi (sum of both n-halves)
        g_partial[(size_t)bj * NROWS + base_i + tid] = rowacc[tid] + rowacc[128 + tid];
        if (!isdiag) {
            // slot bi <- rows of block bj (sum of the 4 m-groups)
            float s = colacc[tid] + colacc[128 + tid] + colacc[256 + tid] + colacc[384 + tid];
            g_partial[(size_t)bi * NROWS + base_j + tid] = s;
        }
    }
}

// ---------------- 3) reduction stage 1 ----------------
__global__ void reduce1_kernel() {
    __shared__ float red[256];
    int r = blockIdx.x * 256 + threadIdx.x;       // 32*256 = 8192 rows
    float s = 0.0f;
    #pragma unroll 8
    for (int p = 0; p < NB; ++p) s += g_partial[(size_t)p * NROWS + r];
    float pv = g_pos[r & (NHALF - 1)];
    s += ex2(pv * LOG2E - SHIFT2);                // the pos logit column
    red[threadIdx.x] = (logf(s) + 20.0f) - pv;    // lse - pos
    __syncthreads();
    #pragma unroll
    for (int o = 128; o; o >>= 1) {
        if (threadIdx.x < o) red[threadIdx.x] += red[threadIdx.x + o];
        __syncthreads();
    }
    if (threadIdx.x == 0) g_blk[blockIdx.x] = red[0];
}

// ---------------- 4) reduction stage 2 ----------------
__global__ void reduce2_kernel(float* __restrict__ out) {
    float v = g_blk[threadIdx.x];
    #pragma unroll
    for (int o = 16; o; o >>= 1) v += __shfl_xor_sync(0xFFFFFFFFu, v, o);
    if (threadIdx.x == 0)
        out[0] = v * (1.0f / ((float)NROWS * (float)NROWS));
}

// ---------------- launcher ----------------
extern "C" void kernel_launch(void* const* d_in, const int* in_sizes, int n_in,
                              void* d_out, int out_size) {
    const float* z1 = (const float*)d_in[0];
    const float* z2 = (const float*)d_in[1];
    float* out = (float*)d_out;
    (void)in_sizes; (void)n_in; (void)out_size;

    normpos_kernel<<<NHALF / 8, 256>>>(z1, z2);
    gemm_kernel<<<NTRI, 256>>>();
    reduce1_kernel<<<32, 256>>>();
    reduce2_kernel<<<1, 32>>>(out);
}